// round 2
// baseline (speedup 1.0000x reference)
#include <cuda_runtime.h>

#define BATCH 32
#define LSEQ  2048
#define DDIM  1024
#define NVOC  320
#define SPLIT 16
#define LSEG  (LSEQ / SPLIT)   // 128

// Scratch (allocation-free rule: __device__ globals)
__device__ float g_w[BATCH * LSEQ];                 // 256 KB
__device__ float g_partial[SPLIT * BATCH * DDIM];   // 8 MB

// ---------------------------------------------------------------------------
// Kernel 1: per-batch weights. One block per batch, 256 threads.
// vq_indices / input_lengths are int32 (JAX x64-disabled downcast).
// ---------------------------------------------------------------------------
__global__ void __launch_bounds__(256)
weights_kernel(const int* __restrict__ lengths,
               const int* __restrict__ vq)
{
    __shared__ int   s_cx[NVOC];
    __shared__ int   s_cy[NVOC];
    __shared__ float s_prob[LSEQ];
    __shared__ float s_sum[8];

    const int b   = blockIdx.x;
    const int tid = threadIdx.x;

    for (int i = tid; i < NVOC; i += 256) { s_cx[i] = 0; s_cy[i] = 0; }
    __syncthreads();

    const int2* vq2 = reinterpret_cast<const int2*>(vq) + (size_t)b * LSEQ;

    int ix[LSEQ / 256], iy[LSEQ / 256];
#pragma unroll
    for (int j = 0; j < LSEQ / 256; j++) {
        int2 v = vq2[tid + j * 256];
        ix[j] = v.x;
        iy[j] = v.y;
        atomicAdd(&s_cx[ix[j]], 1);
        atomicAdd(&s_cy[iy[j]], 1);
    }
    __syncthreads();

    const int len = lengths[b];
    float lsum = 0.0f;
#pragma unroll
    for (int j = 0; j < LSEQ / 256; j++) {
        const int l = tid + j * 256;
        float p = 0.0f;
        if (l < len)
            p = 1.0f / (float)(s_cx[ix[j]] + s_cy[iy[j]]);
        s_prob[l] = p;
        lsum += p;
    }

    // block reduction of lsum
#pragma unroll
    for (int o = 16; o > 0; o >>= 1) lsum += __shfl_xor_sync(0xffffffffu, lsum, o);
    if ((tid & 31) == 0) s_sum[tid >> 5] = lsum;
    __syncthreads();
    if (tid < 8) {
        float s = s_sum[tid];
#pragma unroll
        for (int o = 4; o > 0; o >>= 1) s += __shfl_xor_sync(0xffu, s, o);
        if (tid == 0) s_sum[0] = s;
    }
    __syncthreads();

    const float inv = 1.0f / s_sum[0];
#pragma unroll
    for (int j = 0; j < LSEQ / 256; j++) {
        const int l = tid + j * 256;
        g_w[(size_t)b * LSEQ + l] = s_prob[l] * inv;
    }
}

// ---------------------------------------------------------------------------
// Kernel 2: partial weighted sums over an L-segment.
// grid = (SPLIT, BATCH), 256 threads; each thread owns one float4 of D.
// HBM-bound: reads 256 MB total, fully coalesced 4 KB rows.
// ---------------------------------------------------------------------------
__global__ void __launch_bounds__(256)
gemv_partial_kernel(const float* __restrict__ feat)
{
    const int split = blockIdx.x;   // 0..SPLIT-1
    const int b     = blockIdx.y;   // 0..BATCH-1
    const int tid   = threadIdx.x;  // 0..255 (float4 lane of D)

    __shared__ float s_w[LSEG];
    if (tid < LSEG)
        s_w[tid] = g_w[(size_t)b * LSEQ + split * LSEG + tid];
    __syncthreads();

    // feat slice: input_feature[b, 1, l, d]  (N=2, take last)
    const float4* f4 = reinterpret_cast<const float4*>(
        feat + ((size_t)b * 2 + 1) * (size_t)LSEQ * DDIM
             + (size_t)split * LSEG * DDIM);

    float4 acc = make_float4(0.f, 0.f, 0.f, 0.f);
#pragma unroll 8
    for (int l = 0; l < LSEG; l++) {
        const float  w = s_w[l];
        const float4 v = f4[(size_t)l * (DDIM / 4) + tid];
        acc.x = fmaf(w, v.x, acc.x);
        acc.y = fmaf(w, v.y, acc.y);
        acc.z = fmaf(w, v.z, acc.z);
        acc.w = fmaf(w, v.w, acc.w);
    }

    float4* out4 = reinterpret_cast<float4*>(
        &g_partial[((size_t)split * BATCH + b) * DDIM]);
    out4[tid] = acc;
}

// ---------------------------------------------------------------------------
// Kernel 3: fold SPLIT partials into the output. 8192 float4 lanes.
// ---------------------------------------------------------------------------
__global__ void __launch_bounds__(256)
reduce_kernel(float* __restrict__ out)
{
    const int idx = blockIdx.x * 256 + threadIdx.x;  // float4 index, < B*D/4
    const float4* p = reinterpret_cast<const float4*>(g_partial);
    float4 acc = make_float4(0.f, 0.f, 0.f, 0.f);
#pragma unroll
    for (int s = 0; s < SPLIT; s++) {
        float4 v = p[(size_t)s * (BATCH * DDIM / 4) + idx];
        acc.x += v.x; acc.y += v.y; acc.z += v.z; acc.w += v.w;
    }
    reinterpret_cast<float4*>(out)[idx] = acc;
}

// ---------------------------------------------------------------------------
extern "C" void kernel_launch(void* const* d_in, const int* in_sizes, int n_in,
                              void* d_out, int out_size)
{
    const float* feat    = (const float*)d_in[0];
    const int*   lengths = (const int*)d_in[1];
    const int*   vq      = (const int*)d_in[2];
    float*       out     = (float*)d_out;

    (void)in_sizes; (void)n_in; (void)out_size;

    weights_kernel<<<BATCH, 256>>>(lengths, vq);
    gemv_partial_kernel<<<dim3(SPLIT, BATCH), 256>>>(feat);
    reduce_kernel<<<(BATCH * DDIM / 4) / 256, 256>>>(out);
}

// round 3
// speedup vs baseline: 1.0396x; 1.0396x over previous
#include <cuda_runtime.h>

#define BATCH 32
#define LSEQ  2048
#define DDIM  1024
#define NVOC  320
#define SPLIT 32
#define LSEG  (LSEQ / SPLIT)   // 64

// Scratch (allocation-free rule: __device__ globals)
__device__ float g_w[BATCH * LSEQ];                 // 256 KB
__device__ float g_partial[SPLIT * BATCH * DDIM];   // 16 MB

// ---------------------------------------------------------------------------
// Kernel 1: per-batch weights. One block per batch, 512 threads.
// vq_indices / input_lengths are int32 (JAX x64-disabled downcast).
// ---------------------------------------------------------------------------
#define WTH 512
#define WJ  (LSEQ / WTH)   // 4

__global__ void __launch_bounds__(WTH)
weights_kernel(const int* __restrict__ lengths,
               const int* __restrict__ vq)
{
    __shared__ int   s_cx[NVOC];
    __shared__ int   s_cy[NVOC];
    __shared__ float s_prob[LSEQ];
    __shared__ float s_sum[WTH / 32];

    const int b   = blockIdx.x;
    const int tid = threadIdx.x;

    if (tid < NVOC) { s_cx[tid] = 0; s_cy[tid] = 0; }
    __syncthreads();

    const int2* vq2 = reinterpret_cast<const int2*>(vq) + (size_t)b * LSEQ;

    int ix[WJ], iy[WJ];
#pragma unroll
    for (int j = 0; j < WJ; j++) {
        int2 v = vq2[tid + j * WTH];
        ix[j] = v.x;
        iy[j] = v.y;
        atomicAdd(&s_cx[ix[j]], 1);
        atomicAdd(&s_cy[iy[j]], 1);
    }
    __syncthreads();

    const int len = lengths[b];
    float lsum = 0.0f;
#pragma unroll
    for (int j = 0; j < WJ; j++) {
        const int l = tid + j * WTH;
        float p = 0.0f;
        if (l < len)
            p = __fdividef(1.0f, (float)(s_cx[ix[j]] + s_cy[iy[j]]));
        s_prob[l] = p;
        lsum += p;
    }

    // block reduction of lsum
#pragma unroll
    for (int o = 16; o > 0; o >>= 1) lsum += __shfl_xor_sync(0xffffffffu, lsum, o);
    if ((tid & 31) == 0) s_sum[tid >> 5] = lsum;
    __syncthreads();
    if (tid < WTH / 32) {
        float s = s_sum[tid];
#pragma unroll
        for (int o = (WTH / 64); o > 0; o >>= 1) s += __shfl_xor_sync(0xffffu, s, o);
        if (tid == 0) s_sum[0] = s;
    }
    __syncthreads();

    const float inv = __fdividef(1.0f, s_sum[0]);
#pragma unroll
    for (int j = 0; j < WJ; j++) {
        const int l = tid + j * WTH;
        g_w[(size_t)b * LSEQ + l] = s_prob[l] * inv;
    }
}

// ---------------------------------------------------------------------------
// Kernel 2: partial weighted sums over an L-segment.
// grid = (SPLIT, BATCH) = 1024 blocks (~6.9/SM), 256 threads,
// each thread owns one float4 of D. Reads 256 MB fully coalesced.
// ---------------------------------------------------------------------------
__global__ void __launch_bounds__(256)
gemv_partial_kernel(const float* __restrict__ feat)
{
    const int split = blockIdx.x;   // 0..SPLIT-1
    const int b     = blockIdx.y;   // 0..BATCH-1
    const int tid   = threadIdx.x;  // 0..255 (float4 lane of D)

    __shared__ float s_w[LSEG];
    if (tid < LSEG)
        s_w[tid] = g_w[(size_t)b * LSEQ + split * LSEG + tid];
    __syncthreads();

    // feat slice: input_feature[b, 1, l, d]  (N=2, take last)
    const float4* f4 = reinterpret_cast<const float4*>(
        feat + ((size_t)b * 2 + 1) * (size_t)LSEQ * DDIM
             + (size_t)split * LSEG * DDIM);

    float4 acc = make_float4(0.f, 0.f, 0.f, 0.f);
#pragma unroll 8
    for (int l = 0; l < LSEG; l++) {
        const float  w = s_w[l];
        const float4 v = f4[(size_t)l * (DDIM / 4) + tid];
        acc.x = fmaf(w, v.x, acc.x);
        acc.y = fmaf(w, v.y, acc.y);
        acc.z = fmaf(w, v.z, acc.z);
        acc.w = fmaf(w, v.w, acc.w);
    }

    float4* out4 = reinterpret_cast<float4*>(
        &g_partial[((size_t)split * BATCH + b) * DDIM]);
    out4[tid] = acc;
}

// ---------------------------------------------------------------------------
// Kernel 3: fold SPLIT partials into the output. 8192 float4 lanes.
// ---------------------------------------------------------------------------
__global__ void __launch_bounds__(256)
reduce_kernel(float* __restrict__ out)
{
    const int idx = blockIdx.x * 256 + threadIdx.x;  // float4 index, < B*D/4
    const float4* p = reinterpret_cast<const float4*>(g_partial);
    float4 acc = make_float4(0.f, 0.f, 0.f, 0.f);
#pragma unroll
    for (int s = 0; s < SPLIT; s++) {
        float4 v = p[(size_t)s * (BATCH * DDIM / 4) + idx];
        acc.x += v.x; acc.y += v.y; acc.z += v.z; acc.w += v.w;
    }
    reinterpret_cast<float4*>(out)[idx] = acc;
}

// ---------------------------------------------------------------------------
extern "C" void kernel_launch(void* const* d_in, const int* in_sizes, int n_in,
                              void* d_out, int out_size)
{
    const float* feat    = (const float*)d_in[0];
    const int*   lengths = (const int*)d_in[1];
    const int*   vq      = (const int*)d_in[2];
    float*       out     = (float*)d_out;

    (void)in_sizes; (void)n_in; (void)out_size;

    weights_kernel<<<BATCH, WTH>>>(lengths, vq);
    gemv_partial_kernel<<<dim3(SPLIT, BATCH), 256>>>(feat);
    reduce_kernel<<<(BATCH * DDIM / 4) / 256, 256>>>(out);
}

// round 4
// speedup vs baseline: 1.0917x; 1.0501x over previous
#include <cuda_runtime.h>

#define BATCH 32
#define LSEQ  2048
#define DDIM  1024
#define NVOC  320
#define SPLIT 32
#define LSEG  (LSEQ / SPLIT)   // 64

// Scratch (allocation-free rule: __device__ globals)
__device__ float g_w[BATCH * LSEQ];                 // unnormalized p, 256 KB
__device__ float g_sum[BATCH];                      // per-batch p-sum
__device__ float g_partial[SPLIT * BATCH * DDIM];   // 16 MB

// ---------------------------------------------------------------------------
// Kernel 1: per-batch UNNORMALIZED weights + sum. One block per batch.
// Normalization is deferred to the reduce kernel (removes one phase here).
// vq_indices / input_lengths are int32 (JAX x64-disabled downcast).
// ---------------------------------------------------------------------------
#define WTH 512
#define WJ  (LSEQ / WTH)   // 4

__global__ void __launch_bounds__(WTH)
weights_kernel(const int* __restrict__ lengths,
               const int* __restrict__ vq)
{
    __shared__ int   s_cx[NVOC];
    __shared__ int   s_cy[NVOC];
    __shared__ float s_sum[WTH / 32];

    const int b   = blockIdx.x;
    const int tid = threadIdx.x;

    if (tid < NVOC) { s_cx[tid] = 0; s_cy[tid] = 0; }
    __syncthreads();

    const int2* vq2 = reinterpret_cast<const int2*>(vq) + (size_t)b * LSEQ;

    int ix[WJ], iy[WJ];
#pragma unroll
    for (int j = 0; j < WJ; j++) {
        int2 v = vq2[tid + j * WTH];
        ix[j] = v.x;
        iy[j] = v.y;
        atomicAdd(&s_cx[ix[j]], 1);
        atomicAdd(&s_cy[iy[j]], 1);
    }
    __syncthreads();

    const int len = lengths[b];
    float lsum = 0.0f;
#pragma unroll
    for (int j = 0; j < WJ; j++) {
        const int l = tid + j * WTH;
        float p = 0.0f;
        if (l < len)
            p = __fdividef(1.0f, (float)(s_cx[ix[j]] + s_cy[iy[j]]));
        g_w[(size_t)b * LSEQ + l] = p;      // unnormalized
        lsum += p;
    }

    // block reduction of lsum -> g_sum[b]
#pragma unroll
    for (int o = 16; o > 0; o >>= 1) lsum += __shfl_xor_sync(0xffffffffu, lsum, o);
    if ((tid & 31) == 0) s_sum[tid >> 5] = lsum;
    __syncthreads();
    if (tid < WTH / 32) {
        float s = s_sum[tid];
#pragma unroll
        for (int o = (WTH / 64); o > 0; o >>= 1) s += __shfl_xor_sync(0xffffu, s, o);
        if (tid == 0) g_sum[b] = s;
    }
}

// ---------------------------------------------------------------------------
// Kernel 2: partial weighted sums over an L-segment.
// grid = (SPLIT, BATCH) = 1024 blocks, 256 threads, one float4 of D each.
// Streaming loads (__ldcs): data is read exactly once.
// ---------------------------------------------------------------------------
__global__ void __launch_bounds__(256)
gemv_partial_kernel(const float* __restrict__ feat)
{
    const int split = blockIdx.x;
    const int b     = blockIdx.y;
    const int tid   = threadIdx.x;

    __shared__ float s_w[LSEG];
    if (tid < LSEG)
        s_w[tid] = g_w[(size_t)b * LSEQ + split * LSEG + tid];
    __syncthreads();

    // feat slice: input_feature[b, 1, l, d]  (N=2, take last)
    const float4* f4 = reinterpret_cast<const float4*>(
        feat + ((size_t)b * 2 + 1) * (size_t)LSEQ * DDIM
             + (size_t)split * LSEG * DDIM) + tid;

    float4 acc = make_float4(0.f, 0.f, 0.f, 0.f);
#pragma unroll 16
    for (int l = 0; l < LSEG; l++) {
        const float  w = s_w[l];
        const float4 v = __ldcs(f4 + (size_t)l * (DDIM / 4));
        acc.x = fmaf(w, v.x, acc.x);
        acc.y = fmaf(w, v.y, acc.y);
        acc.z = fmaf(w, v.z, acc.z);
        acc.w = fmaf(w, v.w, acc.w);
    }

    float4* out4 = reinterpret_cast<float4*>(
        &g_partial[((size_t)split * BATCH + b) * DDIM]);
    out4[tid] = acc;
}

// ---------------------------------------------------------------------------
// Kernel 3: fold SPLIT partials and normalize by g_sum[b].
// ---------------------------------------------------------------------------
__global__ void __launch_bounds__(256)
reduce_kernel(float* __restrict__ out)
{
    const int idx = blockIdx.x * 256 + threadIdx.x;  // float4 index, < B*D/4
    const int b   = idx / (DDIM / 4);
    const float4* p = reinterpret_cast<const float4*>(g_partial);
    float4 acc = make_float4(0.f, 0.f, 0.f, 0.f);
#pragma unroll
    for (int s = 0; s < SPLIT; s++) {
        float4 v = p[(size_t)s * (BATCH * DDIM / 4) + idx];
        acc.x += v.x; acc.y += v.y; acc.z += v.z; acc.w += v.w;
    }
    const float inv = __fdividef(1.0f, g_sum[b]);
    acc.x *= inv; acc.y *= inv; acc.z *= inv; acc.w *= inv;
    reinterpret_cast<float4*>(out)[idx] = acc;
}

// ---------------------------------------------------------------------------
extern "C" void kernel_launch(void* const* d_in, const int* in_sizes, int n_in,
                              void* d_out, int out_size)
{
    const float* feat    = (const float*)d_in[0];
    const int*   lengths = (const int*)d_in[1];
    const int*   vq      = (const int*)d_in[2];
    float*       out     = (float*)d_out;

    (void)in_sizes; (void)n_in; (void)out_size;

    weights_kernel<<<BATCH, WTH>>>(lengths, vq);
    gemv_partial_kernel<<<dim3(SPLIT, BATCH), 256>>>(feat);
    reduce_kernel<<<(BATCH * DDIM / 4) / 256, 256>>>(out);
}